// round 2
// baseline (speedup 1.0000x reference)
#include <cuda_runtime.h>
#include <cuda_fp16.h>
#include <cuda_bf16.h>
#include <cstdint>
#include <cstddef>

// Problem shape (fixed by the dataset)
#define BB 4096   // batch rows
#define NN 8192   // memory slots
#define WW 64     // key width
#define NTILES (NN / 128)   // 64 N-tiles per row

// ---------------------------------------------------------------------------
// Scratch (device globals — no allocations allowed)
// ---------------------------------------------------------------------------
__device__ float  g_escale[BB];                    // beta[b] * combined k-normalize scale
__device__ float  g_mscale[NN];                    // 1 / max(||mem_n||, 1e-8)
__device__ __half g_e[(size_t)BB * NN];            // exp(beta*sim) scratch, fp16 (64 MB)
__device__ float  g_partZ[(size_t)BB * NTILES];    // fp32 per-(row,tile) partial sums (1 MB)

// ---------------------------------------------------------------------------
// Kernel 1: per-row scale factors
//   k rows:  k_n = k/max(||k||,1e-12); k_c = k_n/max(||k_n||,1e-8)
//            -> escale = beta * (1/max(nk,1e-12)) * (1/max(||k_n||,1e-8))
//   mem rows: mscale = 1/max(||mem||,1e-8)
// One warp per row; W=64 -> 2 elements per lane.
// ---------------------------------------------------------------------------
__global__ void scales_kernel(const float* __restrict__ K,
                              const float* __restrict__ beta,
                              const float* __restrict__ M)
{
    int w    = (blockIdx.x * blockDim.x + threadIdx.x) >> 5;
    int lane = threadIdx.x & 31;
    if (w >= BB + NN) return;

    const float* src = (w < BB) ? (K + (size_t)w * WW)
                                : (M + (size_t)(w - BB) * WW);
    float x0 = src[lane];
    float x1 = src[lane + 32];
    float ss = x0 * x0 + x1 * x1;
    #pragma unroll
    for (int o = 16; o; o >>= 1) ss += __shfl_xor_sync(0xFFFFFFFFu, ss, o);

    if (lane == 0) {
        float nrm = sqrtf(ss);
        if (w < BB) {
            float a  = 1.0f / fmaxf(nrm, 1e-12f);
            float n2 = nrm * a;                    // ||k_n||
            float b2 = 1.0f / fmaxf(n2, 1e-8f);
            g_escale[w] = beta[w] * a * b2;
        } else {
            g_mscale[w - BB] = 1.0f / fmaxf(nrm, 1e-8f);
        }
    }
}

// ---------------------------------------------------------------------------
// Kernel 2: GEMM + exp:  e[b][n] = exp( dot(k_b, mem_n) * escale[b] * mscale[n] )
// Scales folded into the SMEM tiles at load time -> pure dot product inner
// loop. 128x128 tile, K=64 fully resident (single K step). 8x8 thread tile,
// f32x2 packed FMA (2 FMAs / issue). SMEM ld=66 floats (264B, 8B-aligned):
// A-frag reads are half-warp-broadcast; B-frag LDS.64 stride-66-words hits
// distinct bank pairs across the 16 tx lanes -> conflict-free.
// Epilogue also emits fp32 per-(row,tile) partial sums of e (deterministic,
// no atomics) so the finish kernel gets an exact softmax denominator.
// ---------------------------------------------------------------------------
#define LDT 66
#define GEMM_SMEM (2 * 128 * LDT * 4)

__global__ __launch_bounds__(256) void gemm_exp_kernel(
    const float* __restrict__ K,
    const float* __restrict__ M)
{
    extern __shared__ float sm[];
    float* As = sm;               // [128][LDT]
    float* Bs = sm + 128 * LDT;   // [128][LDT]

    int tid = threadIdx.x;
    int m0  = blockIdx.y << 7;    // * 128
    int n0  = blockIdx.x << 7;    // * 128

    // Load A tile (k rows), folding escale. 128x64 floats = 2048 float4.
    #pragma unroll
    for (int i = 0; i < 8; i++) {
        int f = tid + 256 * i;
        int r = f >> 4;
        int c = (f & 15) << 2;
        float4 v = *(const float4*)(K + (size_t)(m0 + r) * WW + c);
        float sc = g_escale[m0 + r];
        As[r * LDT + c + 0] = v.x * sc;
        As[r * LDT + c + 1] = v.y * sc;
        As[r * LDT + c + 2] = v.z * sc;
        As[r * LDT + c + 3] = v.w * sc;
    }
    // Load B tile (mem rows), folding mscale.
    #pragma unroll
    for (int i = 0; i < 8; i++) {
        int f = tid + 256 * i;
        int r = f >> 4;
        int c = (f & 15) << 2;
        float4 v = *(const float4*)(M + (size_t)(n0 + r) * WW + c);
        float sc = g_mscale[n0 + r];
        Bs[r * LDT + c + 0] = v.x * sc;
        Bs[r * LDT + c + 1] = v.y * sc;
        Bs[r * LDT + c + 2] = v.z * sc;
        Bs[r * LDT + c + 3] = v.w * sc;
    }
    __syncthreads();

    int tx = tid & 15;    // column group
    int ty = tid >> 4;    // row group

    unsigned long long acc[8][8];   // f32x2 partial sums over (even k, odd k)
    #pragma unroll
    for (int i = 0; i < 8; i++)
        #pragma unroll
        for (int j = 0; j < 8; j++) acc[i][j] = 0ull;   // bits of (0.f, 0.f)

    #pragma unroll
    for (int kk = 0; kk < WW; kk += 2) {
        unsigned long long afr[8], bfr[8];
        #pragma unroll
        for (int i = 0; i < 8; i++)
            afr[i] = *(const unsigned long long*)&As[(ty + 16 * i) * LDT + kk];
        #pragma unroll
        for (int j = 0; j < 8; j++)
            bfr[j] = *(const unsigned long long*)&Bs[(tx + 16 * j) * LDT + kk];
        #pragma unroll
        for (int i = 0; i < 8; i++)
            #pragma unroll
            for (int j = 0; j < 8; j++)
                asm volatile("fma.rn.f32x2 %0, %1, %2, %0;"
                             : "+l"(acc[i][j]) : "l"(afr[i]), "l"(bfr[j]));
    }

    // Epilogue: horizontal add of packed pair, exp, fp16 store, and a
    // deterministic fp32 partial-Z per (row, N-tile).
    #pragma unroll
    for (int i = 0; i < 8; i++) {
        int row = m0 + ty + 16 * i;
        __half* erow = g_e + (size_t)row * NN + n0 + tx;
        float psum = 0.0f;
        #pragma unroll
        for (int j = 0; j < 8; j++) {
            float2 v = *reinterpret_cast<float2*>(&acc[i][j]);
            float e  = __expf(v.x + v.y);         // arg in [-1,1]: safe, no max-sub
            psum += e;
            erow[16 * j] = __float2half_rn(e);
        }
        // Reduce across the 16 tx lanes (a contiguous half-warp).
        #pragma unroll
        for (int o = 8; o; o >>= 1)
            psum += __shfl_down_sync(0xFFFFFFFFu, psum, o, 16);
        if (tx == 0)
            g_partZ[(size_t)row * NTILES + blockIdx.x] = psum;
    }
}

// ---------------------------------------------------------------------------
// Kernel 3: per-row finish. One CTA (256 threads) per batch row.
//   Z from g_partZ (exact, deterministic); one fused pass computes
//   gated = g*e/Z + (1-g)*prev into SMEM; stencil+pow into registers;
//   reduce S; scaled store.
// ---------------------------------------------------------------------------
#define FIN_SMEM ((NN + 64) * 4)   // 33 KB: under the 48 KB default

__device__ __forceinline__ float block_reduce_sum(float v, float* red)
{
    int tid = threadIdx.x;
    #pragma unroll
    for (int o = 16; o; o >>= 1) v += __shfl_xor_sync(0xFFFFFFFFu, v, o);
    if ((tid & 31) == 0) red[tid >> 5] = v;
    __syncthreads();
    if (tid < 32) {
        float x = (tid < 8) ? red[tid] : 0.0f;   // 8 warps
        #pragma unroll
        for (int o = 4; o; o >>= 1) x += __shfl_xor_sync(0xFFFFFFFFu, x, o);
        if (tid == 0) red[16] = x;               // disjoint slot
    }
    __syncthreads();
    return red[16];
}

__global__ __launch_bounds__(256) void finish_kernel(
    const float* __restrict__ prev,
    const float* __restrict__ g,
    const float* __restrict__ s,
    const float* __restrict__ gamma,
    float* __restrict__ out)
{
    extern __shared__ float sm[];
    float* buf1 = sm;            // gated row [8192]
    float* red  = sm + NN;       // reduction scratch

    int b   = blockIdx.x;
    int tid = threadIdx.x;

    // Z: sum the 64 exact fp32 partials (deterministic tree).
    float zp = (tid < NTILES) ? g_partZ[(size_t)b * NTILES + tid] : 0.0f;
    float Z  = block_reduce_sum(zp, red);

    float gb = g[b];
    float gm = gamma[b];
    float s0 = s[3 * b], s1 = s[3 * b + 1], s2 = s[3 * b + 2];
    float mx  = fmaxf(s0, fmaxf(s1, s2));
    float es0 = __expf(s0 - mx), es1 = __expf(s1 - mx), es2 = __expf(s2 - mx);
    float inv3 = 1.0f / (es0 + es1 + es2);
    float ss0 = es0 * inv3, ss1 = es1 * inv3, ss2 = es2 * inv3;

    float gcw = gb / Z;          // g * (e/Z)
    float om  = 1.0f - gb;

    // Pass A: load e (half2) + prev (float2), fuse gate, stage gated in SMEM.
    const __half2* e2 = (const __half2*)g_e + (size_t)b * (NN / 2);
    const float2*  p2 = (const float2*)(prev + (size_t)b * NN);
    #pragma unroll
    for (int j = 0; j < 16; j++) {
        int i = tid + 256 * j;
        float2 v = __half22float2(e2[i]);
        float2 p = p2[i];
        v.x = gcw * v.x + om * p.x;
        v.y = gcw * v.y + om * p.y;
        *(float2*)&buf1[2 * i] = v;
    }
    __syncthreads();

    // Pass B: 3-tap non-circular shift + pow into registers, accumulate S.
    float r[32];
    float ssum = 0.0f;
    #pragma unroll
    for (int j = 0; j < 32; j++) {
        int i = tid + 256 * j;
        float left  = (i > 0)      ? buf1[i - 1] : 0.0f;
        float mid   = buf1[i];
        float right = (i < NN - 1) ? buf1[i + 1] : 0.0f;
        float sh = ss0 * left + ss1 * mid + ss2 * right;
        float sp = __powf(sh, gm);
        r[j] = sp;
        ssum += sp;
    }
    float S  = block_reduce_sum(ssum, red);
    float sc = 1.0f / (S + 1e-8f);

    // Pass C: scaled store (coalesced scalar stores).
    float* orow = out + (size_t)b * NN;
    #pragma unroll
    for (int j = 0; j < 32; j++)
        orow[tid + 256 * j] = r[j] * sc;
}

// ---------------------------------------------------------------------------
// Launch. Inputs (metadata order): k, beta, g, s, gamma, prev_weights, memory
// ---------------------------------------------------------------------------
extern "C" void kernel_launch(void* const* d_in, const int* in_sizes, int n_in,
                              void* d_out, int out_size)
{
    const float* K    = (const float*)d_in[0];
    const float* beta = (const float*)d_in[1];
    const float* g    = (const float*)d_in[2];
    const float* s    = (const float*)d_in[3];
    const float* gam  = (const float*)d_in[4];
    const float* prev = (const float*)d_in[5];
    const float* M    = (const float*)d_in[6];
    float* out = (float*)d_out;

    cudaFuncSetAttribute(gemm_exp_kernel,
                         cudaFuncAttributeMaxDynamicSharedMemorySize, GEMM_SMEM);

    // 4096 + 8192 rows, one warp each, 8 warps per block.
    scales_kernel<<<(BB + NN) / 8, 256>>>(K, beta, M);

    // 8192/128 = 64 N-tiles, 4096/128 = 32 M-tiles.
    gemm_exp_kernel<<<dim3(NN / 128, BB / 128), 256, GEMM_SMEM>>>(K, M);

    finish_kernel<<<BB, 256, FIN_SMEM>>>(prev, g, s, gam, out);
}

// round 5
// speedup vs baseline: 1.8201x; 1.8201x over previous
#include <cuda_runtime.h>
#include <cuda_fp16.h>
#include <cuda_bf16.h>
#include <cstdint>
#include <cstddef>

// Problem shape (fixed by the dataset)
#define BB 4096   // batch rows
#define NN 8192   // memory slots
#define WW 64     // key width

// ---------------------------------------------------------------------------
// Scratch (device globals — no allocations allowed)
// ---------------------------------------------------------------------------
__device__ __nv_bfloat16 g_kb[(size_t)BB * WW];  // bf16(k * escale), SW128-preswizzled
__device__ __nv_bfloat16 g_mb[(size_t)NN * WW];  // bf16(mem * mscale), SW128-preswizzled
__device__ __half        g_e[(size_t)BB * NN];   // exp(beta*sim) scratch, fp16 (64 MB)

#define SW128(x) ((x) ^ (((x) >> 3) & 0x70))

__device__ __forceinline__ uint32_t smem_u32(const void* p) {
    uint32_t a;
    asm("{ .reg .u64 t; cvta.to.shared.u64 t, %1; cvt.u32.u64 %0, t; }"
        : "=r"(a) : "l"(p));
    return a;
}

// ---------------------------------------------------------------------------
// Kernel 1: per-row scale factors folded into bf16 operands (pre-swizzled).
//   k rows:  escale = beta * (1/max(||k||,1e-12)) * (1/max(||k_n||,1e-8))
//   mem rows: mscale = 1/max(||mem||,1e-8)
// One warp per row; lane handles cols (2*lane, 2*lane+1).
// ---------------------------------------------------------------------------
__global__ void prep_kernel(const float* __restrict__ K,
                            const float* __restrict__ beta,
                            const float* __restrict__ M)
{
    int w    = (blockIdx.x * blockDim.x + threadIdx.x) >> 5;
    int lane = threadIdx.x & 31;
    if (w >= BB + NN) return;

    bool is_k = (w < BB);
    int  row  = is_k ? w : (w - BB);
    const float* src = (is_k ? K : M) + (size_t)row * WW;

    float x0 = src[2 * lane];
    float x1 = src[2 * lane + 1];
    float ss = x0 * x0 + x1 * x1;
    #pragma unroll
    for (int o = 16; o; o >>= 1) ss += __shfl_xor_sync(0xFFFFFFFFu, ss, o);

    float nrm = sqrtf(ss);
    float sc;
    if (is_k) {
        float a  = 1.0f / fmaxf(nrm, 1e-12f);
        float n2 = nrm * a;                    // ||k_n||
        float b2 = 1.0f / fmaxf(n2, 1e-8f);
        sc = beta[row] * a * b2;
    } else {
        sc = 1.0f / fmaxf(nrm, 1e-8f);
    }

    // Pre-swizzled bf16x2 store: row stride 128B, swizzle permutes 16B units
    // inside each 8-row (1024B) block; a 4B store stays inside one 16B unit.
    uint32_t off = (uint32_t)(row & 7) * 128 + 4 * lane;
    uint32_t sw  = SW128(off);
    char* base = (char*)(is_k ? g_kb : g_mb) + (size_t)(row & ~7) * 128;
    __nv_bfloat162 v = __floats2bfloat162_rn(x0 * sc, x1 * sc);
    *(__nv_bfloat162*)(base + sw) = v;
}

// ---------------------------------------------------------------------------
// Kernel 2: bf16 tensor-core GEMM (mma.sync m16n8k16) + exp epilogue.
//   CTA tile 128x128, K=64. 8 warps in 2(M)x4(N); warp tile 64x32.
//   Operands arrive SW128-preswizzled -> straight 16KB G->S copies, and
//   ldmatrix row addresses recompute the same swizzle (conflict-free).
//   e[b][n] = exp(sim_scaled) stored fp16.
// ---------------------------------------------------------------------------
struct __align__(1024) GemmSmem {
    __nv_bfloat16 A[128 * 64];   // 16 KB
    __nv_bfloat16 B[128 * 64];   // 16 KB
};

// Swizzled byte address of element (row, kbyte) in a tile (row stride 128B).
__device__ __forceinline__ uint32_t tile_addr(uint32_t base, int row, int kbyte) {
    return base + (uint32_t)(row & ~7) * 128 + SW128((uint32_t)(row & 7) * 128 + kbyte);
}

__global__ __launch_bounds__(256) void gemm_exp_kernel()
{
    __shared__ GemmSmem smem;
    int tid  = threadIdx.x;
    int wid  = tid >> 5;
    int lane = tid & 31;
    int n0   = blockIdx.x << 7;
    int m0   = blockIdx.y << 7;

    // Copy pre-swizzled tiles: 16KB each = 1024 uint4 = 256 threads x 4.
    const uint4* gA = (const uint4*)((const char*)g_kb + (size_t)m0 * 128);
    const uint4* gB = (const uint4*)((const char*)g_mb + (size_t)n0 * 128);
    uint4* sA = (uint4*)smem.A;
    uint4* sB = (uint4*)smem.B;
    #pragma unroll
    for (int i = 0; i < 4; i++) {
        int idx = tid + 256 * i;
        sA[idx] = gA[idx];
        sB[idx] = gB[idx];
    }
    __syncthreads();

    uint32_t baseA = smem_u32(smem.A);
    uint32_t baseB = smem_u32(smem.B);

    int warp_m = wid >> 2;           // 0..1 -> 64 rows
    int warp_n = wid & 3;            // 0..3 -> 32 cols
    int m_base = warp_m * 64;
    int n_base = warp_n * 32;

    float acc[4][4][4];              // [mg][ng][frag]
    #pragma unroll
    for (int a = 0; a < 4; a++)
        #pragma unroll
        for (int b = 0; b < 4; b++)
            #pragma unroll
            for (int c = 0; c < 4; c++) acc[a][b][c] = 0.0f;

    #pragma unroll
    for (int ks = 0; ks < 4; ks++) {     // K = 4 x 16
        int k0 = ks * 16;

        // A fragments: 4 x ldmatrix.x4 (m16 x k16 each)
        uint32_t a[4][4];
        #pragma unroll
        for (int mg = 0; mg < 4; mg++) {
            int r  = m_base + mg * 16 + (lane & 15);
            int kb = (k0 + ((lane >> 4) << 3)) * 2;
            uint32_t addr = tile_addr(baseA, r, kb);
            asm volatile("ldmatrix.sync.aligned.m8n8.x4.shared.b16 {%0,%1,%2,%3}, [%4];"
                         : "=r"(a[mg][0]), "=r"(a[mg][1]), "=r"(a[mg][2]), "=r"(a[mg][3])
                         : "r"(addr));
        }
        // B fragments: 2 x ldmatrix.x4, each covers two n8 groups x k16.
        // lanes 0-7: n+0..7 @klo | 8-15: n+0..7 @khi | 16-23: n+8..15 @klo | 24-31: @khi
        uint32_t b[2][4];
        #pragma unroll
        for (int ngp = 0; ngp < 2; ngp++) {
            int n  = n_base + ngp * 16 + (lane & 7) + ((lane >> 4) << 3);
            int kb = (k0 + (((lane >> 3) & 1) << 3)) * 2;
            uint32_t addr = tile_addr(baseB, n, kb);
            asm volatile("ldmatrix.sync.aligned.m8n8.x4.shared.b16 {%0,%1,%2,%3}, [%4];"
                         : "=r"(b[ngp][0]), "=r"(b[ngp][1]), "=r"(b[ngp][2]), "=r"(b[ngp][3])
                         : "r"(addr));
        }
        // MMAs
        #pragma unroll
        for (int mg = 0; mg < 4; mg++)
            #pragma unroll
            for (int ng = 0; ng < 4; ng++) {
                int ngp = ng >> 1, sel = (ng & 1) * 2;
                asm volatile(
                    "mma.sync.aligned.m16n8k16.row.col.f32.bf16.bf16.f32 "
                    "{%0,%1,%2,%3}, {%4,%5,%6,%7}, {%8,%9}, {%0,%1,%2,%3};"
                    : "+f"(acc[mg][ng][0]), "+f"(acc[mg][ng][1]),
                      "+f"(acc[mg][ng][2]), "+f"(acc[mg][ng][3])
                    : "r"(a[mg][0]), "r"(a[mg][1]), "r"(a[mg][2]), "r"(a[mg][3]),
                      "r"(b[ngp][sel]), "r"(b[ngp][sel + 1]));
            }
    }

    // Epilogue: exp -> fp16 g_e. Fragment (m16n8): lane holds
    // rows groupr & groupr+8, cols 2*(lane&3), +1.
    int groupr = lane >> 2;
    int cpair  = (lane & 3) << 1;
    #pragma unroll
    for (int mg = 0; mg < 4; mg++) {
        #pragma unroll
        for (int ng = 0; ng < 4; ng++) {
            int col  = n0 + n_base + ng * 8 + cpair;
            int row0 = m0 + m_base + mg * 16 + groupr;
            float e0 = __expf(acc[mg][ng][0]);
            float e1 = __expf(acc[mg][ng][1]);
            float e2 = __expf(acc[mg][ng][2]);
            float e3 = __expf(acc[mg][ng][3]);
            *(__half2*)(g_e + (size_t)row0 * NN + col)       = __floats2half2_rn(e0, e1);
            *(__half2*)(g_e + (size_t)(row0 + 8) * NN + col) = __floats2half2_rn(e2, e3);
        }
    }
}

// ---------------------------------------------------------------------------
// Kernel 3: per-row finish. One CTA (256 threads) per batch row.
//   Z from the fp16 e row (deterministic fixed-order sum; error ~3e-6 on Z,
//   negligible at the output). Then gate with prev, 3-tap shift, pow,
//   renormalize.
// ---------------------------------------------------------------------------
#define FIN_SMEM ((NN + 64) * 4)   // 33 KB: under the 48 KB default

__device__ __forceinline__ float block_reduce_sum(float v, float* red)
{
    int tid = threadIdx.x;
    #pragma unroll
    for (int o = 16; o; o >>= 1) v += __shfl_xor_sync(0xFFFFFFFFu, v, o);
    if ((tid & 31) == 0) red[tid >> 5] = v;
    __syncthreads();
    if (tid < 32) {
        float x = (tid < 8) ? red[tid] : 0.0f;   // 8 warps
        #pragma unroll
        for (int o = 4; o; o >>= 1) x += __shfl_xor_sync(0xFFFFFFFFu, x, o);
        if (tid == 0) red[16] = x;               // disjoint slot
    }
    __syncthreads();
    return red[16];
}

__global__ __launch_bounds__(256) void finish_kernel(
    const float* __restrict__ prev,
    const float* __restrict__ g,
    const float* __restrict__ s,
    const float* __restrict__ gamma,
    float* __restrict__ out)
{
    extern __shared__ float sm[];
    float* buf = sm;             // e row, then gated row [8192]
    float* red = sm + NN;        // reduction scratch

    int b   = blockIdx.x;
    int tid = threadIdx.x;

    // Pass A: load e (half2), stage to SMEM, accumulate Z.
    const __half2* e2 = (const __half2*)g_e + (size_t)b * (NN / 2);
    float z = 0.0f;
    #pragma unroll
    for (int j = 0; j < 16; j++) {
        int i = tid + 256 * j;
        float2 v = __half22float2(e2[i]);
        *(float2*)&buf[2 * i] = v;
        z += v.x + v.y;
    }
    float Z = block_reduce_sum(z, red);

    float gb = g[b];
    float gm = gamma[b];
    float s0 = s[3 * b], s1 = s[3 * b + 1], s2 = s[3 * b + 2];
    float mx  = fmaxf(s0, fmaxf(s1, s2));
    float es0 = __expf(s0 - mx), es1 = __expf(s1 - mx), es2 = __expf(s2 - mx);
    float inv3 = 1.0f / (es0 + es1 + es2);
    float ss0 = es0 * inv3, ss1 = es1 * inv3, ss2 = es2 * inv3;

    float gcw = gb / Z;          // g * (e/Z)
    float om  = 1.0f - gb;

    // Pass B: gate with prev (each thread rewrites its own slots; the
    // block_reduce's trailing barrier ordered pass A's stores).
    const float2* p2 = (const float2*)(prev + (size_t)b * NN);
    #pragma unroll
    for (int j = 0; j < 16; j++) {
        int i = tid + 256 * j;
        float2 v = *(float2*)&buf[2 * i];
        float2 p = p2[i];
        v.x = gcw * v.x + om * p.x;
        v.y = gcw * v.y + om * p.y;
        *(float2*)&buf[2 * i] = v;
    }
    __syncthreads();

    // Pass C: 3-tap non-circular shift + pow into registers, accumulate S.
    float r[32];
    float ssum = 0.0f;
    #pragma unroll
    for (int j = 0; j < 32; j++) {
        int i = tid + 256 * j;
        float left  = (i > 0)      ? buf[i - 1] : 0.0f;
        float mid   = buf[i];
        float right = (i < NN - 1) ? buf[i + 1] : 0.0f;
        float sh = ss0 * left + ss1 * mid + ss2 * right;
        float sp = __powf(sh, gm);
        r[j] = sp;
        ssum += sp;
    }
    float S  = block_reduce_sum(ssum, red);
    float sc = 1.0f / (S + 1e-8f);

    // Pass D: scaled store (coalesced).
    float* orow = out + (size_t)b * NN;
    #pragma unroll
    for (int j = 0; j < 32; j++)
        orow[tid + 256 * j] = r[j] * sc;
}

// ---------------------------------------------------------------------------
// Launch. Inputs (metadata order): k, beta, g, s, gamma, prev_weights, memory
// ---------------------------------------------------------------------------
extern "C" void kernel_launch(void* const* d_in, const int* in_sizes, int n_in,
                              void* d_out, int out_size)
{
    const float* K    = (const float*)d_in[0];
    const float* beta = (const float*)d_in[1];
    const float* g    = (const float*)d_in[2];
    const float* s    = (const float*)d_in[3];
    const float* gam  = (const float*)d_in[4];
    const float* prev = (const float*)d_in[5];
    const float* M    = (const float*)d_in[6];
    float* out = (float*)d_out;

    // 4096 + 8192 rows, one warp each, 8 warps per block.
    prep_kernel<<<(BB + NN) / 8, 256>>>(K, beta, M);

    // 64 N-tiles x 32 M-tiles, 256 threads.
    gemm_exp_kernel<<<dim3(NN / 128, BB / 128), 256>>>();

    finish_kernel<<<BB, 256, FIN_SMEM>>>(prev, g, s, gam, out);
}

// round 6
// speedup vs baseline: 1.8206x; 1.0003x over previous
#include <cuda_runtime.h>
#include <cuda_fp16.h>
#include <cuda_bf16.h>
#include <cstdint>
#include <cstddef>

// Problem shape (fixed by the dataset)
#define BB 4096   // batch rows
#define NN 8192   // memory slots
#define WW 64     // key width

// ---------------------------------------------------------------------------
// Scratch (device globals — no allocations allowed)
// ---------------------------------------------------------------------------
__device__ __nv_bfloat16 g_kb[(size_t)BB * WW];  // bf16(k * escale), SW128-preswizzled
__device__ __nv_bfloat16 g_mb[(size_t)NN * WW];  // bf16(mem * mscale), SW128-preswizzled
__device__ __half        g_e[(size_t)BB * NN];   // exp(beta*sim) scratch, fp16 (64 MB)

#define SW128(x) ((x) ^ (((x) >> 3) & 0x70))

__device__ __forceinline__ uint32_t smem_u32(const void* p) {
    uint32_t a;
    asm("{ .reg .u64 t; cvta.to.shared.u64 t, %1; cvt.u32.u64 %0, t; }"
        : "=r"(a) : "l"(p));
    return a;
}

// ---------------------------------------------------------------------------
// Kernel 1: per-row scale factors folded into bf16 operands (pre-swizzled).
//   k rows:  escale = beta * (1/max(||k||,1e-12)) * (1/max(||k_n||,1e-8))
//   mem rows: mscale = 1/max(||mem||,1e-8)
// One warp per row; lane handles cols (2*lane, 2*lane+1).
// ---------------------------------------------------------------------------
__global__ void prep_kernel(const float* __restrict__ K,
                            const float* __restrict__ beta,
                            const float* __restrict__ M)
{
    int w    = (blockIdx.x * blockDim.x + threadIdx.x) >> 5;
    int lane = threadIdx.x & 31;
    if (w >= BB + NN) return;

    bool is_k = (w < BB);
    int  row  = is_k ? w : (w - BB);
    const float* src = (is_k ? K : M) + (size_t)row * WW;

    float x0 = src[2 * lane];
    float x1 = src[2 * lane + 1];
    float ss = x0 * x0 + x1 * x1;
    #pragma unroll
    for (int o = 16; o; o >>= 1) ss += __shfl_xor_sync(0xFFFFFFFFu, ss, o);

    float nrm = sqrtf(ss);
    float sc;
    if (is_k) {
        float a  = 1.0f / fmaxf(nrm, 1e-12f);
        float n2 = nrm * a;                    // ||k_n||
        float b2 = 1.0f / fmaxf(n2, 1e-8f);
        sc = beta[row] * a * b2;
    } else {
        sc = 1.0f / fmaxf(nrm, 1e-8f);
    }

    // Pre-swizzled bf16x2 store: row stride 128B, swizzle permutes 16B units
    // inside each 8-row (1024B) block; a 4B store stays inside one 16B unit.
    uint32_t off = (uint32_t)(row & 7) * 128 + 4 * lane;
    uint32_t sw  = SW128(off);
    char* base = (char*)(is_k ? g_kb : g_mb) + (size_t)(row & ~7) * 128;
    __nv_bfloat162 v = __floats2bfloat162_rn(x0 * sc, x1 * sc);
    *(__nv_bfloat162*)(base + sw) = v;
}

// ---------------------------------------------------------------------------
// Kernel 2: bf16 tensor-core GEMM (mma.sync m16n8k16) + exp epilogue.
//   CTA tile 128x128, K=64. 8 warps in 2(M)x4(N); warp tile 64x32.
//   Operands arrive SW128-preswizzled -> straight 16KB G->S copies, and
//   ldmatrix row addresses recompute the same swizzle (conflict-free).
//   e[b][n] = exp(sim_scaled) stored fp16.
// ---------------------------------------------------------------------------
struct __align__(1024) GemmSmem {
    __nv_bfloat16 A[128 * 64];   // 16 KB
    __nv_bfloat16 B[128 * 64];   // 16 KB
};

// Swizzled byte address of element (row, kbyte) in a tile (row stride 128B).
__device__ __forceinline__ uint32_t tile_addr(uint32_t base, int row, int kbyte) {
    return base + (uint32_t)(row & ~7) * 128 + SW128((uint32_t)(row & 7) * 128 + kbyte);
}

__global__ __launch_bounds__(256) void gemm_exp_kernel()
{
    __shared__ GemmSmem smem;
    int tid  = threadIdx.x;
    int wid  = tid >> 5;
    int lane = tid & 31;
    int n0   = blockIdx.x << 7;
    int m0   = blockIdx.y << 7;

    // Copy pre-swizzled tiles: 16KB each = 1024 uint4 = 256 threads x 4.
    const uint4* gA = (const uint4*)((const char*)g_kb + (size_t)m0 * 128);
    const uint4* gB = (const uint4*)((const char*)g_mb + (size_t)n0 * 128);
    uint4* sA = (uint4*)smem.A;
    uint4* sB = (uint4*)smem.B;
    #pragma unroll
    for (int i = 0; i < 4; i++) {
        int idx = tid + 256 * i;
        sA[idx] = gA[idx];
        sB[idx] = gB[idx];
    }
    __syncthreads();

    uint32_t baseA = smem_u32(smem.A);
    uint32_t baseB = smem_u32(smem.B);

    int warp_m = wid >> 2;           // 0..1 -> 64 rows
    int warp_n = wid & 3;            // 0..3 -> 32 cols
    int m_base = warp_m * 64;
    int n_base = warp_n * 32;

    float acc[4][4][4];              // [mg][ng][frag]
    #pragma unroll
    for (int a = 0; a < 4; a++)
        #pragma unroll
        for (int b = 0; b < 4; b++)
            #pragma unroll
            for (int c = 0; c < 4; c++) acc[a][b][c] = 0.0f;

    #pragma unroll
    for (int ks = 0; ks < 4; ks++) {     // K = 4 x 16
        int k0 = ks * 16;

        // A fragments: 4 x ldmatrix.x4 (m16 x k16 each)
        uint32_t a[4][4];
        #pragma unroll
        for (int mg = 0; mg < 4; mg++) {
            int r  = m_base + mg * 16 + (lane & 15);
            int kb = (k0 + ((lane >> 4) << 3)) * 2;
            uint32_t addr = tile_addr(baseA, r, kb);
            asm volatile("ldmatrix.sync.aligned.m8n8.x4.shared.b16 {%0,%1,%2,%3}, [%4];"
                         : "=r"(a[mg][0]), "=r"(a[mg][1]), "=r"(a[mg][2]), "=r"(a[mg][3])
                         : "r"(addr));
        }
        // B fragments: 2 x ldmatrix.x4, each covers two n8 groups x k16.
        // lanes 0-7: n+0..7 @klo | 8-15: n+0..7 @khi | 16-23: n+8..15 @klo | 24-31: @khi
        uint32_t b[2][4];
        #pragma unroll
        for (int ngp = 0; ngp < 2; ngp++) {
            int n  = n_base + ngp * 16 + (lane & 7) + ((lane >> 4) << 3);
            int kb = (k0 + (((lane >> 3) & 1) << 3)) * 2;
            uint32_t addr = tile_addr(baseB, n, kb);
            asm volatile("ldmatrix.sync.aligned.m8n8.x4.shared.b16 {%0,%1,%2,%3}, [%4];"
                         : "=r"(b[ngp][0]), "=r"(b[ngp][1]), "=r"(b[ngp][2]), "=r"(b[ngp][3])
                         : "r"(addr));
        }
        // MMAs
        #pragma unroll
        for (int mg = 0; mg < 4; mg++)
            #pragma unroll
            for (int ng = 0; ng < 4; ng++) {
                int ngp = ng >> 1, sel = (ng & 1) * 2;
                asm volatile(
                    "mma.sync.aligned.m16n8k16.row.col.f32.bf16.bf16.f32 "
                    "{%0,%1,%2,%3}, {%4,%5,%6,%7}, {%8,%9}, {%0,%1,%2,%3};"
                    : "+f"(acc[mg][ng][0]), "+f"(acc[mg][ng][1]),
                      "+f"(acc[mg][ng][2]), "+f"(acc[mg][ng][3])
                    : "r"(a[mg][0]), "r"(a[mg][1]), "r"(a[mg][2]), "r"(a[mg][3]),
                      "r"(b[ngp][sel]), "r"(b[ngp][sel + 1]));
            }
    }

    // Epilogue: exp -> fp16 g_e. Fragment (m16n8): lane holds
    // rows groupr & groupr+8, cols 2*(lane&3), +1.
    int groupr = lane >> 2;
    int cpair  = (lane & 3) << 1;
    #pragma unroll
    for (int mg = 0; mg < 4; mg++) {
        #pragma unroll
        for (int ng = 0; ng < 4; ng++) {
            int col  = n0 + n_base + ng * 8 + cpair;
            int row0 = m0 + m_base + mg * 16 + groupr;
            float e0 = __expf(acc[mg][ng][0]);
            float e1 = __expf(acc[mg][ng][1]);
            float e2 = __expf(acc[mg][ng][2]);
            float e3 = __expf(acc[mg][ng][3]);
            *(__half2*)(g_e + (size_t)row0 * NN + col)       = __floats2half2_rn(e0, e1);
            *(__half2*)(g_e + (size_t)(row0 + 8) * NN + col) = __floats2half2_rn(e2, e3);
        }
    }
}

// ---------------------------------------------------------------------------
// Kernel 3: per-row finish. One CTA (256 threads) per batch row.
//   Z from the fp16 e row (deterministic fixed-order sum; error ~3e-6 on Z,
//   negligible at the output). Then gate with prev, 3-tap shift, pow,
//   renormalize.
// ---------------------------------------------------------------------------
#define FIN_SMEM ((NN + 64) * 4)   // 33 KB: under the 48 KB default

__device__ __forceinline__ float block_reduce_sum(float v, float* red)
{
    int tid = threadIdx.x;
    #pragma unroll
    for (int o = 16; o; o >>= 1) v += __shfl_xor_sync(0xFFFFFFFFu, v, o);
    if ((tid & 31) == 0) red[tid >> 5] = v;
    __syncthreads();
    if (tid < 32) {
        float x = (tid < 8) ? red[tid] : 0.0f;   // 8 warps
        #pragma unroll
        for (int o = 4; o; o >>= 1) x += __shfl_xor_sync(0xFFFFFFFFu, x, o);
        if (tid == 0) red[16] = x;               // disjoint slot
    }
    __syncthreads();
    return red[16];
}

__global__ __launch_bounds__(256) void finish_kernel(
    const float* __restrict__ prev,
    const float* __restrict__ g,
    const float* __restrict__ s,
    const float* __restrict__ gamma,
    float* __restrict__ out)
{
    extern __shared__ float sm[];
    float* buf = sm;             // e row, then gated row [8192]
    float* red = sm + NN;        // reduction scratch

    int b   = blockIdx.x;
    int tid = threadIdx.x;

    // Pass A: load e (half2), stage to SMEM, accumulate Z.
    const __half2* e2 = (const __half2*)g_e + (size_t)b * (NN / 2);
    float z = 0.0f;
    #pragma unroll
    for (int j = 0; j < 16; j++) {
        int i = tid + 256 * j;
        float2 v = __half22float2(e2[i]);
        *(float2*)&buf[2 * i] = v;
        z += v.x + v.y;
    }
    float Z = block_reduce_sum(z, red);

    float gb = g[b];
    float gm = gamma[b];
    float s0 = s[3 * b], s1 = s[3 * b + 1], s2 = s[3 * b + 2];
    float mx  = fmaxf(s0, fmaxf(s1, s2));
    float es0 = __expf(s0 - mx), es1 = __expf(s1 - mx), es2 = __expf(s2 - mx);
    float inv3 = 1.0f / (es0 + es1 + es2);
    float ss0 = es0 * inv3, ss1 = es1 * inv3, ss2 = es2 * inv3;

    float gcw = gb / Z;          // g * (e/Z)
    float om  = 1.0f - gb;

    // Pass B: gate with prev (each thread rewrites its own slots; the
    // block_reduce's trailing barrier ordered pass A's stores).
    const float2* p2 = (const float2*)(prev + (size_t)b * NN);
    #pragma unroll
    for (int j = 0; j < 16; j++) {
        int i = tid + 256 * j;
        float2 v = *(float2*)&buf[2 * i];
        float2 p = p2[i];
        v.x = gcw * v.x + om * p.x;
        v.y = gcw * v.y + om * p.y;
        *(float2*)&buf[2 * i] = v;
    }
    __syncthreads();

    // Pass C: 3-tap non-circular shift + pow into registers, accumulate S.
    float r[32];
    float ssum = 0.0f;
    #pragma unroll
    for (int j = 0; j < 32; j++) {
        int i = tid + 256 * j;
        float left  = (i > 0)      ? buf[i - 1] : 0.0f;
        float mid   = buf[i];
        float right = (i < NN - 1) ? buf[i + 1] : 0.0f;
        float sh = ss0 * left + ss1 * mid + ss2 * right;
        float sp = __powf(sh, gm);
        r[j] = sp;
        ssum += sp;
    }
    float S  = block_reduce_sum(ssum, red);
    float sc = 1.0f / (S + 1e-8f);

    // Pass D: scaled store (coalesced).
    float* orow = out + (size_t)b * NN;
    #pragma unroll
    for (int j = 0; j < 32; j++)
        orow[tid + 256 * j] = r[j] * sc;
}

// ---------------------------------------------------------------------------
// Launch. Inputs (metadata order): k, beta, g, s, gamma, prev_weights, memory
// ---------------------------------------------------------------------------
extern "C" void kernel_launch(void* const* d_in, const int* in_sizes, int n_in,
                              void* d_out, int out_size)
{
    const float* K    = (const float*)d_in[0];
    const float* beta = (const float*)d_in[1];
    const float* g    = (const float*)d_in[2];
    const float* s    = (const float*)d_in[3];
    const float* gam  = (const float*)d_in[4];
    const float* prev = (const float*)d_in[5];
    const float* M    = (const float*)d_in[6];
    float* out = (float*)d_out;

    // 4096 + 8192 rows, one warp each, 8 warps per block.
    prep_kernel<<<(BB + NN) / 8, 256>>>(K, beta, M);

    // 64 N-tiles x 32 M-tiles, 256 threads.
    gemm_exp_kernel<<<dim3(NN / 128, BB / 128), 256>>>();

    finish_kernel<<<BB, 256, FIN_SMEM>>>(prev, g, s, gam, out);
}